// round 1
// baseline (speedup 1.0000x reference)
#include <cuda_runtime.h>
#include <math.h>

#define BB 4
#define TT 2048
#define CC 1024
#define HH 16
#define DD 64
#define MM (BB*TT)

// Scratch (device globals per harness rules; no runtime allocation)
__device__ float g_q[(size_t)BB*HH*TT*DD];
__device__ float g_k[(size_t)BB*HH*TT*DD];
__device__ float g_v[(size_t)BB*HH*TT*DD];
__device__ float g_attn[(size_t)MM*CC];

// ---------------------------------------------------------------------------
// GEMM: out[m][n] = sum_k A[m][k] * W[n][k]   (A: [M,K], W: [N,K] row-major)
// K = CC = 1024 fixed. Tile 64x64x16, 256 threads, 4x4 microtile.
// REMAP=true  -> write to [B,H,T,D] layout (for Q/K/V)
// REMAP=false -> write row-major [M,N]
// ---------------------------------------------------------------------------
template<bool REMAP>
__global__ __launch_bounds__(256) void gemm_nt(const float* __restrict__ A,
                                               const float* __restrict__ W,
                                               float* __restrict__ out) {
    const int K = CC;
    __shared__ float sA[16][68];
    __shared__ float sB[16][68];

    const int tid = threadIdx.x;
    const int tx = tid & 15;
    const int ty = tid >> 4;
    const int row0 = blockIdx.y * 64;
    const int col0 = blockIdx.x * 64;

    float acc[4][4] = {};

    const int lm  = tid >> 2;         // 0..63
    const int lk4 = (tid & 3) << 2;   // 0,4,8,12
    const float* Aptr = A + (size_t)(row0 + lm) * K + lk4;
    const float* Wptr = W + (size_t)(col0 + lm) * K + lk4;

    for (int kb = 0; kb < K; kb += 16) {
        float4 a4 = *(const float4*)(Aptr + kb);
        float4 b4 = *(const float4*)(Wptr + kb);
        __syncthreads();  // protect smem from previous compute
        sA[lk4 + 0][lm] = a4.x; sA[lk4 + 1][lm] = a4.y;
        sA[lk4 + 2][lm] = a4.z; sA[lk4 + 3][lm] = a4.w;
        sB[lk4 + 0][lm] = b4.x; sB[lk4 + 1][lm] = b4.y;
        sB[lk4 + 2][lm] = b4.z; sB[lk4 + 3][lm] = b4.w;
        __syncthreads();
#pragma unroll
        for (int kk = 0; kk < 16; kk++) {
            float4 av = *(const float4*)&sA[kk][ty << 2];
            float4 bv = *(const float4*)&sB[kk][tx << 2];
            acc[0][0] += av.x * bv.x; acc[0][1] += av.x * bv.y;
            acc[0][2] += av.x * bv.z; acc[0][3] += av.x * bv.w;
            acc[1][0] += av.y * bv.x; acc[1][1] += av.y * bv.y;
            acc[1][2] += av.y * bv.z; acc[1][3] += av.y * bv.w;
            acc[2][0] += av.z * bv.x; acc[2][1] += av.z * bv.y;
            acc[2][2] += av.z * bv.z; acc[2][3] += av.z * bv.w;
            acc[3][0] += av.w * bv.x; acc[3][1] += av.w * bv.y;
            acc[3][2] += av.w * bv.z; acc[3][3] += av.w * bv.w;
        }
    }

    // Store 4x4 microtile, float4 along n (d stays within one head: col0 % 64 == 0)
#pragma unroll
    for (int i = 0; i < 4; i++) {
        const int m = row0 + (ty << 2) + i;
        const int n0 = col0 + (tx << 2);
        float4 o = make_float4(acc[i][0], acc[i][1], acc[i][2], acc[i][3]);
        if (REMAP) {
            const int b = m / TT, t = m % TT;
            const int h = n0 >> 6, d = n0 & 63;
            *(float4*)(out + (((size_t)(b * HH + h) * TT + t) << 6) + d) = o;
        } else {
            *(float4*)(out + (size_t)m * CC + n0) = o;
        }
    }
}

// ---------------------------------------------------------------------------
// Flash attention (fp32, causal). One CTA = one (b,h) x 64-row Q tile.
// Online softmax; K/V tiles streamed through dynamic smem.
// ---------------------------------------------------------------------------
__global__ __launch_bounds__(256) void flash_kernel() {
    extern __shared__ float sm[];
    float* Qs = sm;                 // [64][64]  stride 64 (vec4-friendly)
    float* Ks = Qs + 64 * 64;       // [64][65]  stride 65 (conflict-free scalar)
    float* Vs = Ks + 64 * 65;       // [64][64]  stride 64
    float* Ps = Vs + 64 * 64;       // [64][65]  stride 65

    const int tid = threadIdx.x;
    const int tx = tid & 15;
    const int ty = tid >> 4;
    const int q0 = blockIdx.x * 64;
    const int bh = blockIdx.y;      // b*H + h
    const int b = bh / HH, h = bh % HH;

    const float* Qg = g_q + (size_t)bh * TT * DD;
    const float* Kg = g_k + (size_t)bh * TT * DD;
    const float* Vg = g_v + (size_t)bh * TT * DD;

    // Load Q tile (64x64), coalesced float4
    for (int i = tid; i < 1024; i += 256) {
        const int r = i >> 4, dv = (i & 15) << 2;
        float4 qv = *(const float4*)(Qg + (size_t)(q0 + r) * DD + dv);
        *(float4*)&Qs[r * 64 + dv] = qv;
    }

    float m_i[4], l_i[4], acc[4][4] = {};
#pragma unroll
    for (int i = 0; i < 4; i++) { m_i[i] = -INFINITY; l_i[i] = 0.f; }

    const int ktiles = (q0 >> 6) + 1;
    const unsigned FULL = 0xffffffffu;

    for (int kt = 0; kt < ktiles; kt++) {
        const int k0 = kt << 6;
        __syncthreads();  // previous iteration done with Ks/Vs/Ps
        for (int i = tid; i < 1024; i += 256) {
            const int r = i >> 4, dv = (i & 15) << 2;
            float4 kv = *(const float4*)(Kg + (size_t)(k0 + r) * DD + dv);
            Ks[r * 65 + dv + 0] = kv.x; Ks[r * 65 + dv + 1] = kv.y;
            Ks[r * 65 + dv + 2] = kv.z; Ks[r * 65 + dv + 3] = kv.w;
            float4 vv = *(const float4*)(Vg + (size_t)(k0 + r) * DD + dv);
            *(float4*)&Vs[r * 64 + dv] = vv;
        }
        __syncthreads();

        // S = Q * K^T  (4x4 microtile per thread)
        float s[4][4] = {};
#pragma unroll 8
        for (int dd = 0; dd < 64; dd++) {
            float qv[4], kv[4];
#pragma unroll
            for (int i = 0; i < 4; i++) qv[i] = Qs[((ty << 2) + i) * 64 + dd];
#pragma unroll
            for (int j = 0; j < 4; j++) kv[j] = Ks[((tx << 2) + j) * 65 + dd];
#pragma unroll
            for (int i = 0; i < 4; i++)
#pragma unroll
                for (int j = 0; j < 4; j++) s[i][j] += qv[i] * kv[j];
        }

        const bool diag = (kt == ktiles - 1);
#pragma unroll
        for (int i = 0; i < 4; i++) {
            const int qg = q0 + (ty << 2) + i;
#pragma unroll
            for (int j = 0; j < 4; j++) {
                s[i][j] *= 0.125f;  // 1/sqrt(64)
                if (diag && (k0 + (tx << 2) + j > qg)) s[i][j] = -INFINITY;
            }
        }

        // Online softmax per row (row spread over 16 tx lanes)
#pragma unroll
        for (int i = 0; i < 4; i++) {
            float mx = fmaxf(fmaxf(s[i][0], s[i][1]), fmaxf(s[i][2], s[i][3]));
#pragma unroll
            for (int off = 8; off; off >>= 1)
                mx = fmaxf(mx, __shfl_xor_sync(FULL, mx, off, 16));
            const float m_new = fmaxf(m_i[i], mx);
            const float corr = __expf(m_i[i] - m_new);
            float rs = 0.f;
#pragma unroll
            for (int j = 0; j < 4; j++) {
                const float p = __expf(s[i][j] - m_new);
                Ps[((ty << 2) + i) * 65 + (tx << 2) + j] = p;
                rs += p;
            }
#pragma unroll
            for (int off = 8; off; off >>= 1)
                rs += __shfl_xor_sync(FULL, rs, off, 16);
            l_i[i] = l_i[i] * corr + rs;
            m_i[i] = m_new;
#pragma unroll
            for (int j = 0; j < 4; j++) acc[i][j] *= corr;
        }
        __syncthreads();  // Ps visible

        // O += P * V
#pragma unroll 8
        for (int kk = 0; kk < 64; kk++) {
            float pv[4];
#pragma unroll
            for (int i = 0; i < 4; i++) pv[i] = Ps[((ty << 2) + i) * 65 + kk];
            float4 vv = *(const float4*)&Vs[kk * 64 + (tx << 2)];
#pragma unroll
            for (int i = 0; i < 4; i++) {
                acc[i][0] += pv[i] * vv.x; acc[i][1] += pv[i] * vv.y;
                acc[i][2] += pv[i] * vv.z; acc[i][3] += pv[i] * vv.w;
            }
        }
    }

    // Normalize + store to [B,T,C] scratch
#pragma unroll
    for (int i = 0; i < 4; i++) {
        const float inv = 1.0f / l_i[i];
        const int q = q0 + (ty << 2) + i;
        float4 o = make_float4(acc[i][0] * inv, acc[i][1] * inv,
                               acc[i][2] * inv, acc[i][3] * inv);
        *(float4*)(g_attn + (size_t)(b * TT + q) * CC + h * DD + (tx << 2)) = o;
    }
}

// ---------------------------------------------------------------------------
extern "C" void kernel_launch(void* const* d_in, const int* in_sizes, int n_in,
                              void* d_out, int out_size) {
    const float* x  = (const float*)d_in[0];
    const float* Wq = (const float*)d_in[1];
    const float* Wk = (const float*)d_in[2];
    const float* Wv = (const float*)d_in[3];
    const float* Wo = (const float*)d_in[4];
    float* out = (float*)d_out;

    float *q, *k, *v, *attn;
    cudaGetSymbolAddress((void**)&q, g_q);
    cudaGetSymbolAddress((void**)&k, g_k);
    cudaGetSymbolAddress((void**)&v, g_v);
    cudaGetSymbolAddress((void**)&attn, g_attn);

    dim3 gproj(CC / 64, MM / 64);  // (16, 128)

    gemm_nt<true><<<gproj, 256>>>(x, Wq, q);
    gemm_nt<true><<<gproj, 256>>>(x, Wk, k);
    gemm_nt<true><<<gproj, 256>>>(x, Wv, v);

    const size_t shmem = (size_t)(64 * 64 + 64 * 65 + 64 * 64 + 64 * 65) * sizeof(float);
    cudaFuncSetAttribute(flash_kernel, cudaFuncAttributeMaxDynamicSharedMemorySize,
                         (int)shmem);
    flash_kernel<<<dim3(TT / 64, BB * HH), 256, shmem>>>();

    gemm_nt<false><<<gproj, 256>>>(attn, Wo, out);
}

// round 5
// speedup vs baseline: 1.0723x; 1.0723x over previous
#include <cuda_runtime.h>
#include <cuda_bf16.h>
#include <math.h>
#include <stdint.h>

#define BB 4
#define TT 2048
#define CC 1024
#define HH 16
#define DD 64
#define MM (BB*TT)

// ---------------- scratch (device globals; no runtime alloc) ----------------
__device__ float g_q[(size_t)BB*HH*TT*DD];
__device__ float g_k[(size_t)BB*HH*TT*DD];
__device__ float g_v[(size_t)BB*HH*TT*DD];
__device__ float g_attn[(size_t)MM*CC];
__device__ __nv_bfloat16 g_xh[(size_t)MM*CC], g_xl[(size_t)MM*CC];
__device__ __nv_bfloat16 g_ah[(size_t)MM*CC], g_al[(size_t)MM*CC];
__device__ __nv_bfloat16 g_wh[4][(size_t)CC*CC], g_wl[4][(size_t)CC*CC];

// ---------------- base-ISA tensor helpers (compute_103-safe) ----------------
__device__ __forceinline__ uint32_t smem_u32(const void* p) {
    uint32_t a;
    asm("{ .reg .u64 t; cvta.to.shared.u64 t, %1; cvt.u32.u64 %0, t; }"
        : "=r"(a) : "l"(p));
    return a;
}
__device__ __forceinline__ void cp16(uint32_t dst, const void* src) {
    asm volatile("cp.async.cg.shared.global [%0], [%1], 16;" :: "r"(dst), "l"(src));
}
__device__ __forceinline__ void cp_commit() { asm volatile("cp.async.commit_group;"); }
template<int N> __device__ __forceinline__ void cp_wait() {
    asm volatile("cp.async.wait_group %0;" :: "n"(N));
}
__device__ __forceinline__ void ldsm4(uint32_t* r, uint32_t addr) {
    asm volatile("ldmatrix.sync.aligned.m8n8.x4.shared.b16 {%0,%1,%2,%3}, [%4];"
                 : "=r"(r[0]), "=r"(r[1]), "=r"(r[2]), "=r"(r[3]) : "r"(addr));
}
__device__ __forceinline__ void mma16816(float* d, const uint32_t* a, const uint32_t* b) {
    asm volatile(
        "mma.sync.aligned.m16n8k16.row.col.f32.bf16.bf16.f32 "
        "{%0,%1,%2,%3}, {%4,%5,%6,%7}, {%8,%9}, {%0,%1,%2,%3};"
        : "+f"(d[0]), "+f"(d[1]), "+f"(d[2]), "+f"(d[3])
        : "r"(a[0]), "r"(a[1]), "r"(a[2]), "r"(a[3]), "r"(b[0]), "r"(b[1]));
}

// ---------------------------------------------------------------------------
// fp32 -> (bf16 hi, bf16 lo) split
// ---------------------------------------------------------------------------
__global__ __launch_bounds__(256) void split_bf16(const float* __restrict__ src,
                                                  __nv_bfloat16* __restrict__ hi,
                                                  __nv_bfloat16* __restrict__ lo,
                                                  int n4) {
    int i = blockIdx.x * 256 + threadIdx.x;
    if (i >= n4) return;
    float4 v = ((const float4*)src)[i];
    __nv_bfloat16 h0 = __float2bfloat16(v.x), h1 = __float2bfloat16(v.y);
    __nv_bfloat16 h2 = __float2bfloat16(v.z), h3 = __float2bfloat16(v.w);
    __nv_bfloat16 l0 = __float2bfloat16(v.x - __bfloat162float(h0));
    __nv_bfloat16 l1 = __float2bfloat16(v.y - __bfloat162float(h1));
    __nv_bfloat16 l2 = __float2bfloat16(v.z - __bfloat162float(h2));
    __nv_bfloat16 l3 = __float2bfloat16(v.w - __bfloat162float(h3));
    ((__nv_bfloat162*)hi)[2 * i]     = __nv_bfloat162(h0, h1);
    ((__nv_bfloat162*)hi)[2 * i + 1] = __nv_bfloat162(h2, h3);
    ((__nv_bfloat162*)lo)[2 * i]     = __nv_bfloat162(l0, l1);
    ((__nv_bfloat162*)lo)[2 * i + 1] = __nv_bfloat162(l2, l3);
}

// ---------------------------------------------------------------------------
// HMMA split-bf16 GEMM: out[m][n] = sum_k A[m][k]*B[n][k]
// CTA tile 128x128, K-chunk 32, 8 warps (2x4), warp tile 64x32.
// Double-buffered cp.async. Rows padded to 40 bf16 (80 B) for conflict-free
// ldmatrix.
// ---------------------------------------------------------------------------
#define ROWB 80                    // bytes per smem row (32 bf16 + pad)
#define MATB (128 * ROWB)          // one matrix (128 rows)
#define STAGEB (4 * MATB)          // Ah | Al | Bh | Bl
#define NCHUNK (CC / 32)           // 32 K-chunks

template<int REMAP>
__global__ __launch_bounds__(256)
void mma_gemm(const __nv_bfloat16* __restrict__ Ah_g, const __nv_bfloat16* __restrict__ Al_g,
              const __nv_bfloat16* __restrict__ Bh_g, const __nv_bfloat16* __restrict__ Bl_g,
              float* __restrict__ out) {
    extern __shared__ __align__(128) char smem[];

    const int tid = threadIdx.x;
    const int wid = tid >> 5;
    const int lane = tid & 31;
    const int m0 = blockIdx.y * 128;
    const int n0 = blockIdx.x * 128;
    const uint32_t sbase = smem_u32(smem);

    // global sources (bytes); each row is CC bf16 = 2048 B
    const char* srcs[4] = {
        (const char*)(Ah_g + (size_t)m0 * CC), (const char*)(Al_g + (size_t)m0 * CC),
        (const char*)(Bh_g + (size_t)n0 * CC), (const char*)(Bl_g + (size_t)n0 * CC)};

    // -- async-load one K-chunk (32 cols) of all 4 matrices into stage st --
    auto stage_load = [&](int kc, int st) {
        const uint32_t dst0 = sbase + st * STAGEB;
        const size_t koff = (size_t)kc * 64;  // 32 bf16 = 64 B
#pragma unroll
        for (int mtx = 0; mtx < 4; mtx++) {
#pragma unroll
            for (int h = 0; h < 2; h++) {
                const int idx = h * 256 + tid;         // 0..511
                const int r = idx >> 2, c = idx & 3;   // row, 16B-col
                cp16(dst0 + mtx * MATB + r * ROWB + c * 16,
                     srcs[mtx] + (size_t)r * 2048 + koff + c * 16);
            }
        }
    };

    const int wm = wid >> 2, wn = wid & 3;       // 2 x 4 warp grid
    const int g = lane >> 2, tig = lane & 3;

    float acc[4][4][4] = {};                      // [mt][nt][4]

    // per-lane ldmatrix address offsets (bytes, within a matrix)
    const int a_row = wm * 64 + (lane & 15);
    const int a_col = (lane >> 4) * 16;           // 8 bf16 = 16 B
    const int b_row = wn * 32 + (lane & 7) + ((lane >> 4) & 1) * 8;
    const int b_col = ((lane >> 3) & 1) * 16;

    stage_load(0, 0);
    cp_commit();

    for (int c = 0; c < NCHUNK; c++) {
        const int st = c & 1;
        if (c + 1 < NCHUNK) { stage_load(c + 1, (c + 1) & 1); cp_commit(); cp_wait<1>(); }
        else                { cp_wait<0>(); }
        __syncthreads();

        const uint32_t sAh = sbase + st * STAGEB;
        const uint32_t sAl = sAh + MATB;
        const uint32_t sBh = sAh + 2 * MATB;
        const uint32_t sBl = sAh + 3 * MATB;

#pragma unroll
        for (int s = 0; s < 2; s++) {             // two k16 steps per chunk
            const int k16 = s * 32;               // 16 bf16 = 32 B
            uint32_t afh[4][4], afl[4][4], bfh[2][4], bfl[2][4];
#pragma unroll
            for (int mt = 0; mt < 4; mt++) {
                const uint32_t ao = (a_row + mt * 16) * ROWB + a_col + k16;
                ldsm4(afh[mt], sAh + ao);
                ldsm4(afl[mt], sAl + ao);
            }
#pragma unroll
            for (int np = 0; np < 2; np++) {
                const uint32_t bo = (b_row + np * 16) * ROWB + b_col + k16;
                ldsm4(bfh[np], sBh + bo);
                ldsm4(bfl[np], sBl + bo);
            }
#pragma unroll
            for (int mt = 0; mt < 4; mt++)
#pragma unroll
                for (int nt = 0; nt < 4; nt++) {
                    const int np = nt >> 1, hf = (nt & 1) * 2;
                    mma16816(acc[mt][nt], afh[mt], &bfh[np][hf]);  // Ah*Bh
                    mma16816(acc[mt][nt], afh[mt], &bfl[np][hf]);  // Ah*Bl
                    mma16816(acc[mt][nt], afl[mt], &bfh[np][hf]);  // Al*Bh
                }
        }
        __syncthreads();
    }

    // -- epilogue: each lane owns rows (g, g+8), cols 2*tig..2*tig+1 per tile --
#pragma unroll
    for (int mt = 0; mt < 4; mt++) {
#pragma unroll
        for (int half = 0; half < 2; half++) {
            const int m = m0 + wm * 64 + mt * 16 + g + half * 8;
            float* dst;
            if (REMAP) {
                const int b = m >> 11, t = m & 2047;
                dst = out + (((size_t)b * HH) * TT + t) * DD;  // + h*TT*DD + d
            } else {
                dst = out + (size_t)m * CC;
            }
#pragma unroll
            for (int nt = 0; nt < 4; nt++) {
                const int n = n0 + wn * 32 + nt * 8 + tig * 2;
                float2 v = make_float2(acc[mt][nt][half * 2], acc[mt][nt][half * 2 + 1]);
                if (REMAP) {
                    const int h = n >> 6, d = n & 63;
                    *(float2*)(dst + (size_t)h * TT * DD + d) = v;
                } else {
                    *(float2*)(dst + n) = v;
                }
            }
        }
    }
}

// ---------------------------------------------------------------------------
// Flash attention (fp32, causal) — unchanged (known good).
// ---------------------------------------------------------------------------
__global__ __launch_bounds__(256) void flash_kernel() {
    extern __shared__ float sm[];
    float* Qs = sm;
    float* Ks = Qs + 64 * 64;
    float* Vs = Ks + 64 * 65;
    float* Ps = Vs + 64 * 64;

    const int tid = threadIdx.x;
    const int tx = tid & 15;
    const int ty = tid >> 4;
    const int q0 = blockIdx.x * 64;
    const int bh = blockIdx.y;
    const int b = bh / HH, h = bh % HH;

    const float* Qg = g_q + (size_t)bh * TT * DD;
    const float* Kg = g_k + (size_t)bh * TT * DD;
    const float* Vg = g_v + (size_t)bh * TT * DD;

    for (int i = tid; i < 1024; i += 256) {
        const int r = i >> 4, dv = (i & 15) << 2;
        float4 qv = *(const float4*)(Qg + (size_t)(q0 + r) * DD + dv);
        *(float4*)&Qs[r * 64 + dv] = qv;
    }

    float m_i[4], l_i[4], acc[4][4] = {};
#pragma unroll
    for (int i = 0; i < 4; i++) { m_i[i] = -INFINITY; l_i[i] = 0.f; }

    const int ktiles = (q0 >> 6) + 1;
    const unsigned FULL = 0xffffffffu;

    for (int kt = 0; kt < ktiles; kt++) {
        const int k0 = kt << 6;
        __syncthreads();
        for (int i = tid; i < 1024; i += 256) {
            const int r = i >> 4, dv = (i & 15) << 2;
            float4 kv = *(const float4*)(Kg + (size_t)(k0 + r) * DD + dv);
            Ks[r * 65 + dv + 0] = kv.x; Ks[r * 65 + dv + 1] = kv.y;
            Ks[r * 65 + dv + 2] = kv.z; Ks[r * 65 + dv + 3] = kv.w;
            float4 vv = *(const float4*)(Vg + (size_t)(k0 + r) * DD + dv);
            *(float4*)&Vs[r * 64 + dv] = vv;
        }
        __syncthreads();

        float s[4][4] = {};
#pragma unroll 8
        for (int dd = 0; dd < 64; dd++) {
            float qv[4], kv[4];
#pragma unroll
            for (int i = 0; i < 4; i++) qv[i] = Qs[((ty << 2) + i) * 64 + dd];
#pragma unroll
            for (int j = 0; j < 4; j++) kv[j] = Ks[((tx << 2) + j) * 65 + dd];
#pragma unroll
            for (int i = 0; i < 4; i++)
#pragma unroll
                for (int j = 0; j < 4; j++) s[i][j] += qv[i] * kv[j];
        }

        const bool diag = (kt == ktiles - 1);
#pragma unroll
        for (int i = 0; i < 4; i++) {
            const int qg = q0 + (ty << 2) + i;
#pragma unroll
            for (int j = 0; j < 4; j++) {
                s[i][j] *= 0.125f;
                if (diag && (k0 + (tx << 2) + j > qg)) s[i][j] = -INFINITY;
            }
        }

#pragma unroll
        for (int i = 0; i < 4; i++) {
            float mx = fmaxf(fmaxf(s[i][0], s[i][1]), fmaxf(s[i][2], s[i][3]));
#pragma unroll
            for (int off = 8; off; off >>= 1)
                mx = fmaxf(mx, __shfl_xor_sync(FULL, mx, off, 16));
            const float m_new = fmaxf(m_i[i], mx);
            const float corr = __expf(m_i[i] - m_new);
            float rs = 0.f;
#pragma unroll
            for (int j = 0; j < 4; j++) {
                const float p = __expf(s[i][j] - m_new);
                Ps[((ty << 2) + i) * 65 + (tx << 2) + j] = p;
                rs += p;
            }
#pragma unroll
            for (int off = 8; off; off >>= 1)
                rs += __shfl_xor_sync(FULL, rs, off, 16);
            l_i[i] = l_i[i] * corr + rs;
            m_i[i] = m_new;
#pragma unroll
            for (int j = 0; j < 4; j++) acc[i][j] *= corr;
        }
        __syncthreads();

#pragma unroll 8
        for (int kk = 0; kk < 64; kk++) {
            float pv[4];
#pragma unroll
            for (int i = 0; i < 4; i++) pv[i] = Ps[((ty << 2) + i) * 65 + kk];
            float4 vv = *(const float4*)&Vs[kk * 64 + (tx << 2)];
#pragma unroll
            for (int i = 0; i < 4; i++) {
                acc[i][0] += pv[i] * vv.x; acc[i][1] += pv[i] * vv.y;
                acc[i][2] += pv[i] * vv.z; acc[i][3] += pv[i] * vv.w;
            }
        }
    }

#pragma unroll
    for (int i = 0; i < 4; i++) {
        const float inv = 1.0f / l_i[i];
        const int q = q0 + (ty << 2) + i;
        float4 o = make_float4(acc[i][0] * inv, acc[i][1] * inv,
                               acc[i][2] * inv, acc[i][3] * inv);
        *(float4*)(g_attn + (size_t)(b * TT + q) * CC + h * DD + (tx << 2)) = o;
    }
}

// ---------------------------------------------------------------------------
extern "C" void kernel_launch(void* const* d_in, const int* in_sizes, int n_in,
                              void* d_out, int out_size) {
    const float* x  = (const float*)d_in[0];
    const float* Wq = (const float*)d_in[1];
    const float* Wk = (const float*)d_in[2];
    const float* Wv = (const float*)d_in[3];
    const float* Wo = (const float*)d_in[4];
    float* out = (float*)d_out;

    float *q, *k, *v, *attn;
    cudaGetSymbolAddress((void**)&q, g_q);
    cudaGetSymbolAddress((void**)&k, g_k);
    cudaGetSymbolAddress((void**)&v, g_v);
    cudaGetSymbolAddress((void**)&attn, g_attn);
    __nv_bfloat16 *xh, *xl, *ah, *al, *wh, *wl;
    cudaGetSymbolAddress((void**)&xh, g_xh);
    cudaGetSymbolAddress((void**)&xl, g_xl);
    cudaGetSymbolAddress((void**)&ah, g_ah);
    cudaGetSymbolAddress((void**)&al, g_al);
    cudaGetSymbolAddress((void**)&wh, g_wh);
    cudaGetSymbolAddress((void**)&wl, g_wl);

    const float* Ws[4] = {Wq, Wk, Wv, Wo};

    split_bf16<<<(MM * CC / 4 + 255) / 256, 256>>>(x, xh, xl, MM * CC / 4);
    for (int i = 0; i < 4; i++)
        split_bf16<<<(CC * CC / 4 + 255) / 256, 256>>>(
            Ws[i], wh + (size_t)i * CC * CC, wl + (size_t)i * CC * CC, CC * CC / 4);

    const int gemm_smem = 2 * STAGEB;  // 81920 B
    cudaFuncSetAttribute(mma_gemm<1>, cudaFuncAttributeMaxDynamicSharedMemorySize, gemm_smem);
    cudaFuncSetAttribute(mma_gemm<0>, cudaFuncAttributeMaxDynamicSharedMemorySize, gemm_smem);

    dim3 gg(CC / 128, MM / 128);  // (8, 64)
    mma_gemm<1><<<gg, 256, gemm_smem>>>(xh, xl, wh + 0 * (size_t)CC * CC, wl + 0 * (size_t)CC * CC, q);
    mma_gemm<1><<<gg, 256, gemm_smem>>>(xh, xl, wh + 1 * (size_t)CC * CC, wl + 1 * (size_t)CC * CC, k);
    mma_gemm<1><<<gg, 256, gemm_smem>>>(xh, xl, wh + 2 * (size_t)CC * CC, wl + 2 * (size_t)CC * CC, v);

    const size_t shmem = (size_t)(64 * 64 + 64 * 65 + 64 * 64 + 64 * 65) * sizeof(float);
    cudaFuncSetAttribute(flash_kernel, cudaFuncAttributeMaxDynamicSharedMemorySize, (int)shmem);
    flash_kernel<<<dim3(TT / 64, BB * HH), 256, shmem>>>();

    split_bf16<<<(MM * CC / 4 + 255) / 256, 256>>>(attn, ah, al, MM * CC / 4);
    mma_gemm<0><<<gg, 256, gemm_smem>>>(ah, al, wh + 3 * (size_t)CC * CC, wl + 3 * (size_t)CC * CC, out);
}

// round 6
// speedup vs baseline: 1.2684x; 1.1829x over previous
#include <cuda_runtime.h>
#include <cuda_bf16.h>
#include <math.h>
#include <stdint.h>

#define BB 4
#define TT 2048
#define CC 1024
#define HH 16
#define DD 64
#define MM (BB*TT)

// ---------------- scratch (device globals; no runtime alloc) ----------------
__device__ float g_q[(size_t)BB*HH*TT*DD];
__device__ float g_k[(size_t)BB*HH*TT*DD];
__device__ float g_v[(size_t)BB*HH*TT*DD];
__device__ __nv_bfloat16 g_xh[(size_t)MM*CC], g_xl[(size_t)MM*CC];
__device__ __nv_bfloat16 g_ah[(size_t)MM*CC], g_al[(size_t)MM*CC];
__device__ __nv_bfloat16 g_wh[4][(size_t)CC*CC], g_wl[4][(size_t)CC*CC];

// ---------------- base-ISA tensor helpers (compute_103-safe) ----------------
__device__ __forceinline__ uint32_t smem_u32(const void* p) {
    uint32_t a;
    asm("{ .reg .u64 t; cvta.to.shared.u64 t, %1; cvt.u32.u64 %0, t; }"
        : "=r"(a) : "l"(p));
    return a;
}
__device__ __forceinline__ void cp16(uint32_t dst, const void* src) {
    asm volatile("cp.async.cg.shared.global [%0], [%1], 16;" :: "r"(dst), "l"(src));
}
__device__ __forceinline__ void cp_commit() { asm volatile("cp.async.commit_group;"); }
template<int N> __device__ __forceinline__ void cp_wait() {
    asm volatile("cp.async.wait_group %0;" :: "n"(N));
}
__device__ __forceinline__ void ldsm4(uint32_t* r, uint32_t addr) {
    asm volatile("ldmatrix.sync.aligned.m8n8.x4.shared.b16 {%0,%1,%2,%3}, [%4];"
                 : "=r"(r[0]), "=r"(r[1]), "=r"(r[2]), "=r"(r[3]) : "r"(addr));
}
__device__ __forceinline__ void mma16816(float* d, const uint32_t* a, const uint32_t* b) {
    asm volatile(
        "mma.sync.aligned.m16n8k16.row.col.f32.bf16.bf16.f32 "
        "{%0,%1,%2,%3}, {%4,%5,%6,%7}, {%8,%9}, {%0,%1,%2,%3};"
        : "+f"(d[0]), "+f"(d[1]), "+f"(d[2]), "+f"(d[3])
        : "r"(a[0]), "r"(a[1]), "r"(a[2]), "r"(a[3]), "r"(b[0]), "r"(b[1]));
}

// ---------------------------------------------------------------------------
// fp32 -> (bf16 hi, bf16 lo) split
// ---------------------------------------------------------------------------
__global__ __launch_bounds__(256) void split_bf16(const float* __restrict__ src,
                                                  __nv_bfloat16* __restrict__ hi,
                                                  __nv_bfloat16* __restrict__ lo,
                                                  int n4) {
    int i = blockIdx.x * 256 + threadIdx.x;
    if (i >= n4) return;
    float4 v = ((const float4*)src)[i];
    __nv_bfloat16 h0 = __float2bfloat16(v.x), h1 = __float2bfloat16(v.y);
    __nv_bfloat16 h2 = __float2bfloat16(v.z), h3 = __float2bfloat16(v.w);
    __nv_bfloat16 l0 = __float2bfloat16(v.x - __bfloat162float(h0));
    __nv_bfloat16 l1 = __float2bfloat16(v.y - __bfloat162float(h1));
    __nv_bfloat16 l2 = __float2bfloat16(v.z - __bfloat162float(h2));
    __nv_bfloat16 l3 = __float2bfloat16(v.w - __bfloat162float(h3));
    ((__nv_bfloat162*)hi)[2 * i]     = __nv_bfloat162(h0, h1);
    ((__nv_bfloat162*)hi)[2 * i + 1] = __nv_bfloat162(h2, h3);
    ((__nv_bfloat162*)lo)[2 * i]     = __nv_bfloat162(l0, l1);
    ((__nv_bfloat162*)lo)[2 * i + 1] = __nv_bfloat162(l2, l3);
}

// ---------------------------------------------------------------------------
// HMMA split-bf16 GEMM (unchanged from R5; near HMMA floor).
// ---------------------------------------------------------------------------
#define ROWB 80
#define MATB (128 * ROWB)
#define STAGEB (4 * MATB)
#define NCHUNK (CC / 32)

template<int REMAP>
__global__ __launch_bounds__(256)
void mma_gemm(const __nv_bfloat16* __restrict__ Ah_g, const __nv_bfloat16* __restrict__ Al_g,
              const __nv_bfloat16* __restrict__ Bh_g, const __nv_bfloat16* __restrict__ Bl_g,
              float* __restrict__ out) {
    extern __shared__ __align__(128) char smem[];

    const int tid = threadIdx.x;
    const int wid = tid >> 5;
    const int lane = tid & 31;
    const int m0 = blockIdx.y * 128;
    const int n0 = blockIdx.x * 128;
    const uint32_t sbase = smem_u32(smem);

    const char* srcs[4] = {
        (const char*)(Ah_g + (size_t)m0 * CC), (const char*)(Al_g + (size_t)m0 * CC),
        (const char*)(Bh_g + (size_t)n0 * CC), (const char*)(Bl_g + (size_t)n0 * CC)};

    auto stage_load = [&](int kc, int st) {
        const uint32_t dst0 = sbase + st * STAGEB;
        const size_t koff = (size_t)kc * 64;
#pragma unroll
        for (int mtx = 0; mtx < 4; mtx++) {
#pragma unroll
            for (int h = 0; h < 2; h++) {
                const int idx = h * 256 + tid;
                const int r = idx >> 2, c = idx & 3;
                cp16(dst0 + mtx * MATB + r * ROWB + c * 16,
                     srcs[mtx] + (size_t)r * 2048 + koff + c * 16);
            }
        }
    };

    const int wm = wid >> 2, wn = wid & 3;
    const int g = lane >> 2, tig = lane & 3;

    float acc[4][4][4] = {};

    const int a_row = wm * 64 + (lane & 15);
    const int a_col = (lane >> 4) * 16;
    const int b_row = wn * 32 + (lane & 7) + ((lane >> 4) & 1) * 8;
    const int b_col = ((lane >> 3) & 1) * 16;

    stage_load(0, 0);
    cp_commit();

    for (int c = 0; c < NCHUNK; c++) {
        const int st = c & 1;
        if (c + 1 < NCHUNK) { stage_load(c + 1, (c + 1) & 1); cp_commit(); cp_wait<1>(); }
        else                { cp_wait<0>(); }
        __syncthreads();

        const uint32_t sAh = sbase + st * STAGEB;
        const uint32_t sAl = sAh + MATB;
        const uint32_t sBh = sAh + 2 * MATB;
        const uint32_t sBl = sAh + 3 * MATB;

#pragma unroll
        for (int s = 0; s < 2; s++) {
            const int k16 = s * 32;
            uint32_t afh[4][4], afl[4][4], bfh[2][4], bfl[2][4];
#pragma unroll
            for (int mt = 0; mt < 4; mt++) {
                const uint32_t ao = (a_row + mt * 16) * ROWB + a_col + k16;
                ldsm4(afh[mt], sAh + ao);
                ldsm4(afl[mt], sAl + ao);
            }
#pragma unroll
            for (int np = 0; np < 2; np++) {
                const uint32_t bo = (b_row + np * 16) * ROWB + b_col + k16;
                ldsm4(bfh[np], sBh + bo);
                ldsm4(bfl[np], sBl + bo);
            }
#pragma unroll
            for (int mt = 0; mt < 4; mt++)
#pragma unroll
                for (int nt = 0; nt < 4; nt++) {
                    const int np = nt >> 1, hf = (nt & 1) * 2;
                    mma16816(acc[mt][nt], afh[mt], &bfh[np][hf]);
                    mma16816(acc[mt][nt], afh[mt], &bfl[np][hf]);
                    mma16816(acc[mt][nt], afl[mt], &bfh[np][hf]);
                }
        }
        __syncthreads();
    }

#pragma unroll
    for (int mt = 0; mt < 4; mt++) {
#pragma unroll
        for (int half = 0; half < 2; half++) {
            const int m = m0 + wm * 64 + mt * 16 + g + half * 8;
            float* dst;
            if (REMAP) {
                const int b = m >> 11, t = m & 2047;
                dst = out + (((size_t)b * HH) * TT + t) * DD;
            } else {
                dst = out + (size_t)m * CC;
            }
#pragma unroll
            for (int nt = 0; nt < 4; nt++) {
                const int n = n0 + wn * 32 + nt * 8 + tig * 2;
                float2 v = make_float2(acc[mt][nt][half * 2], acc[mt][nt][half * 2 + 1]);
                if (REMAP) {
                    const int h = n >> 6, d = n & 63;
                    *(float2*)(dst + (size_t)h * TT * DD + d) = v;
                } else {
                    *(float2*)(dst + n) = v;
                }
            }
        }
    }
}

// ---------------------------------------------------------------------------
// Flash attention (fp32, causal) — vectorized-LDS microkernel.
// Smem: Qs [64][64], Ks/Vs/Ps [64][68] (float4-aligned, conflict-benign).
// Epilogue writes bf16 hi/lo of O directly (feeds Wo GEMM; no fp32 roundtrip).
// ---------------------------------------------------------------------------
#define FS 68   // padded row stride (floats) for Ks/Vs/Ps

__global__ __launch_bounds__(256) void flash_kernel() {
    extern __shared__ float sm[];
    float* Qs = sm;                  // [64][64]
    float* Ks = Qs + 64 * 64;        // [64][FS]
    float* Vs = Ks + 64 * FS;        // [64][FS]
    float* Ps = Vs + 64 * FS;        // [64][FS]

    const int tid = threadIdx.x;
    const int tx = tid & 15;
    const int ty = tid >> 4;
    const int q0 = (gridDim.x - 1 - blockIdx.x) * 64;   // heavy tiles first
    const int bh = blockIdx.y;
    const int b = bh / HH, h = bh % HH;

    const float* Qg = g_q + (size_t)bh * TT * DD;
    const float* Kg = g_k + (size_t)bh * TT * DD;
    const float* Vg = g_v + (size_t)bh * TT * DD;

    for (int i = tid; i < 1024; i += 256) {
        const int r = i >> 4, dv = (i & 15) << 2;
        *(float4*)&Qs[r * 64 + dv] = *(const float4*)(Qg + (size_t)(q0 + r) * DD + dv);
    }

    float m_i[4], l_i[4], acc[4][4] = {};
#pragma unroll
    for (int i = 0; i < 4; i++) { m_i[i] = -INFINITY; l_i[i] = 0.f; }

    const int ktiles = (q0 >> 6) + 1;
    const unsigned FULL = 0xffffffffu;

    for (int kt = 0; kt < ktiles; kt++) {
        const int k0 = kt << 6;
        __syncthreads();
        for (int i = tid; i < 1024; i += 256) {
            const int r = i >> 4, dv = (i & 15) << 2;
            *(float4*)&Ks[r * FS + dv] = *(const float4*)(Kg + (size_t)(k0 + r) * DD + dv);
            *(float4*)&Vs[r * FS + dv] = *(const float4*)(Vg + (size_t)(k0 + r) * DD + dv);
        }
        __syncthreads();

        // ---- S = Q * K^T : float4 over d; 8 LDS.128 per 64 FFMA ----
        float s[4][4] = {};
#pragma unroll 4
        for (int d4 = 0; d4 < 16; d4++) {
            float4 qv[4], kv[4];
#pragma unroll
            for (int i = 0; i < 4; i++) qv[i] = *(const float4*)&Qs[((ty << 2) + i) * 64 + (d4 << 2)];
#pragma unroll
            for (int j = 0; j < 4; j++) kv[j] = *(const float4*)&Ks[((tx << 2) + j) * FS + (d4 << 2)];
#pragma unroll
            for (int i = 0; i < 4; i++)
#pragma unroll
                for (int j = 0; j < 4; j++)
                    s[i][j] += qv[i].x * kv[j].x + qv[i].y * kv[j].y +
                               qv[i].z * kv[j].z + qv[i].w * kv[j].w;
        }

        const bool diag = (kt == ktiles - 1);
#pragma unroll
        for (int i = 0; i < 4; i++) {
            const int qg = q0 + (ty << 2) + i;
#pragma unroll
            for (int j = 0; j < 4; j++) {
                s[i][j] *= 0.125f;
                if (diag && (k0 + (tx << 2) + j > qg)) s[i][j] = -INFINITY;
            }
        }

        // ---- online softmax (row spread over 16 tx lanes) ----
#pragma unroll
        for (int i = 0; i < 4; i++) {
            float mx = fmaxf(fmaxf(s[i][0], s[i][1]), fmaxf(s[i][2], s[i][3]));
#pragma unroll
            for (int off = 8; off; off >>= 1)
                mx = fmaxf(mx, __shfl_xor_sync(FULL, mx, off, 16));
            const float m_new = fmaxf(m_i[i], mx);
            const float corr = __expf(m_i[i] - m_new);
            float4 p4;
            p4.x = __expf(s[i][0] - m_new); p4.y = __expf(s[i][1] - m_new);
            p4.z = __expf(s[i][2] - m_new); p4.w = __expf(s[i][3] - m_new);
            *(float4*)&Ps[((ty << 2) + i) * FS + (tx << 2)] = p4;
            float rs = p4.x + p4.y + p4.z + p4.w;
#pragma unroll
            for (int off = 8; off; off >>= 1)
                rs += __shfl_xor_sync(FULL, rs, off, 16);
            l_i[i] = l_i[i] * corr + rs;
            m_i[i] = m_new;
#pragma unroll
            for (int j = 0; j < 4; j++) acc[i][j] *= corr;
        }
        __syncthreads();

        // ---- O += P * V : float4 over k; 8 LDS.128 per 64 FFMA ----
#pragma unroll 4
        for (int k4 = 0; k4 < 16; k4++) {
            float4 vv[4], pr[4];
#pragma unroll
            for (int kq = 0; kq < 4; kq++) vv[kq] = *(const float4*)&Vs[((k4 << 2) + kq) * FS + (tx << 2)];
#pragma unroll
            for (int i = 0; i < 4; i++) pr[i] = *(const float4*)&Ps[((ty << 2) + i) * FS + (k4 << 2)];
#pragma unroll
            for (int i = 0; i < 4; i++) {
                acc[i][0] += pr[i].x * vv[0].x + pr[i].y * vv[1].x + pr[i].z * vv[2].x + pr[i].w * vv[3].x;
                acc[i][1] += pr[i].x * vv[0].y + pr[i].y * vv[1].y + pr[i].z * vv[2].y + pr[i].w * vv[3].y;
                acc[i][2] += pr[i].x * vv[0].z + pr[i].y * vv[1].z + pr[i].z * vv[2].z + pr[i].w * vv[3].z;
                acc[i][3] += pr[i].x * vv[0].w + pr[i].y * vv[1].w + pr[i].z * vv[2].w + pr[i].w * vv[3].w;
            }
        }
    }

    // ---- normalize + bf16 hi/lo split directly into Wo GEMM inputs ----
#pragma unroll
    for (int i = 0; i < 4; i++) {
        const float inv = 1.0f / l_i[i];
        const int q = q0 + (ty << 2) + i;
        const size_t base = (size_t)(b * TT + q) * CC + h * DD + (tx << 2);
        __nv_bfloat16 hh[4], ll[4];
#pragma unroll
        for (int j = 0; j < 4; j++) {
            const float v = acc[i][j] * inv;
            hh[j] = __float2bfloat16(v);
            ll[j] = __float2bfloat16(v - __bfloat162float(hh[j]));
        }
        *(__nv_bfloat162*)(g_ah + base)     = __nv_bfloat162(hh[0], hh[1]);
        *(__nv_bfloat162*)(g_ah + base + 2) = __nv_bfloat162(hh[2], hh[3]);
        *(__nv_bfloat162*)(g_al + base)     = __nv_bfloat162(ll[0], ll[1]);
        *(__nv_bfloat162*)(g_al + base + 2) = __nv_bfloat162(ll[2], ll[3]);
    }
}

// ---------------------------------------------------------------------------
extern "C" void kernel_launch(void* const* d_in, const int* in_sizes, int n_in,
                              void* d_out, int out_size) {
    const float* x  = (const float*)d_in[0];
    const float* Wq = (const float*)d_in[1];
    const float* Wk = (const float*)d_in[2];
    const float* Wv = (const float*)d_in[3];
    const float* Wo = (const float*)d_in[4];
    float* out = (float*)d_out;

    float *q, *k, *v;
    cudaGetSymbolAddress((void**)&q, g_q);
    cudaGetSymbolAddress((void**)&k, g_k);
    cudaGetSymbolAddress((void**)&v, g_v);
    __nv_bfloat16 *xh, *xl, *ah, *al, *wh, *wl;
    cudaGetSymbolAddress((void**)&xh, g_xh);
    cudaGetSymbolAddress((void**)&xl, g_xl);
    cudaGetSymbolAddress((void**)&ah, g_ah);
    cudaGetSymbolAddress((void**)&al, g_al);
    cudaGetSymbolAddress((void**)&wh, g_wh);
    cudaGetSymbolAddress((void**)&wl, g_wl);

    const float* Ws[4] = {Wq, Wk, Wv, Wo};

    split_bf16<<<(MM * CC / 4 + 255) / 256, 256>>>(x, xh, xl, MM * CC / 4);
    for (int i = 0; i < 4; i++)
        split_bf16<<<(CC * CC / 4 + 255) / 256, 256>>>(
            Ws[i], wh + (size_t)i * CC * CC, wl + (size_t)i * CC * CC, CC * CC / 4);

    const int gemm_smem = 2 * STAGEB;
    cudaFuncSetAttribute(mma_gemm<1>, cudaFuncAttributeMaxDynamicSharedMemorySize, gemm_smem);
    cudaFuncSetAttribute(mma_gemm<0>, cudaFuncAttributeMaxDynamicSharedMemorySize, gemm_smem);

    dim3 gg(CC / 128, MM / 128);
    mma_gemm<1><<<gg, 256, gemm_smem>>>(xh, xl, wh + 0 * (size_t)CC * CC, wl + 0 * (size_t)CC * CC, q);
    mma_gemm<1><<<gg, 256, gemm_smem>>>(xh, xl, wh + 1 * (size_t)CC * CC, wl + 1 * (size_t)CC * CC, k);
    mma_gemm<1><<<gg, 256, gemm_smem>>>(xh, xl, wh + 2 * (size_t)CC * CC, wl + 2 * (size_t)CC * CC, v);

    const size_t shmem = (size_t)(64 * 64 + 3 * 64 * FS) * sizeof(float);
    cudaFuncSetAttribute(flash_kernel, cudaFuncAttributeMaxDynamicSharedMemorySize, (int)shmem);
    flash_kernel<<<dim3(TT / 64, BB * HH), 256, shmem>>>();

    mma_gemm<0><<<gg, 256, gemm_smem>>>(ah, al, wh + 3 * (size_t)CC * CC, wl + 3 * (size_t)CC * CC, out);
}